// round 14
// baseline (speedup 1.0000x reference)
#include <cuda_runtime.h>
#include <cuda_fp16.h>
#include <stdint.h>

#define NB 16
#define NN 2048
#define NTOT (NB*NN)
#define KNB 16
#define IND 128
#define OUTD 256
#define NEDGE (NTOT*KNB)

// ---------------- scratch ----------------
__device__ float d_sqn[NTOT];
__device__ int   d_nbr[NTOT*KNB];
__device__ __half d_xh[(size_t)NTOT*IND];
__device__ __half d_xl[(size_t)NTOT*IND];
__device__ __half d_axh[(size_t)NTOT*IND];
__device__ __half d_axl[(size_t)NTOT*IND];
__device__ uint32_t d_h1p[(size_t)NTOT*OUTD];
__device__ __half d_ahh[(size_t)NTOT*OUTD];
__device__ __half d_ahl[(size_t)NTOT*OUTD];
__device__ __half d_w1h[IND*OUTD],  d_w1l[IND*OUTD];
__device__ __half d_w2h[OUTD*OUTD], d_w2l[OUTD*OUTD];
__device__ __half d_wsh[IND*OUTD],  d_wsl[IND*OUTD];

// ---------------- helpers ----------------
__device__ __forceinline__ uint32_t smem_u32(const void* p) {
    uint32_t a;
    asm("{ .reg .u64 t; cvta.to.shared.u64 t, %1; cvt.u32.u64 %0, t; }" : "=r"(a) : "l"(p));
    return a;
}
__device__ __forceinline__ void cpa16(uint32_t dst, const void* src) {
    asm volatile("cp.async.cg.shared.global [%0], [%1], 16;" :: "r"(dst), "l"(src));
}
__device__ __forceinline__ void cp_commit() { asm volatile("cp.async.commit_group;"); }
__device__ __forceinline__ void cp_wait0()  { asm volatile("cp.async.wait_group 0;"); }
__device__ __forceinline__ void ldsm4(uint32_t* r, uint32_t a) {
    asm volatile("ldmatrix.sync.aligned.m8n8.x4.shared.b16 {%0,%1,%2,%3}, [%4];"
        : "=r"(r[0]), "=r"(r[1]), "=r"(r[2]), "=r"(r[3]) : "r"(a));
}
__device__ __forceinline__ void ldsm2t(uint32_t* r, uint32_t a) {
    asm volatile("ldmatrix.sync.aligned.m8n8.x2.trans.shared.b16 {%0,%1}, [%2];"
        : "=r"(r[0]), "=r"(r[1]) : "r"(a));
}
__device__ __forceinline__ void mma16816(float* c, const uint32_t* a, const uint32_t* b) {
    asm volatile("mma.sync.aligned.m16n8k16.row.col.f32.f16.f16.f32 "
        "{%0,%1,%2,%3}, {%4,%5,%6,%7}, {%8,%9}, {%0,%1,%2,%3};"
        : "+f"(c[0]), "+f"(c[1]), "+f"(c[2]), "+f"(c[3])
        : "r"(a[0]), "r"(a[1]), "r"(a[2]), "r"(a[3]), "r"(b[0]), "r"(b[1]));
}

// ---------------- prep: sqn + 2-way fp16 split of x ----------------
__global__ __launch_bounds__(256) void k_prep(const float* __restrict__ x) {
    const int row = blockIdx.x * 8 + (threadIdx.x >> 5);
    const int lane = threadIdx.x & 31;
    float4 v = *(const float4*)(x + (size_t)row * IND + lane * 4);
    float s = v.x*v.x + v.y*v.y + v.z*v.z + v.w*v.w;
#pragma unroll
    for (int o = 16; o > 0; o >>= 1) s += __shfl_xor_sync(0xffffffffu, s, o);
    if (lane == 0) d_sqn[row] = s;
    float f[4] = {v.x, v.y, v.z, v.w};
    __half h[4], l[4];
#pragma unroll
    for (int j = 0; j < 4; j++) {
        h[j] = __float2half_rn(f[j]);
        l[j] = __float2half_rn(f[j] - __half2float(h[j]));
    }
    const size_t o = (size_t)row * IND + lane * 4;
    *(uint2*)(d_xh + o) = *(uint2*)h;
    *(uint2*)(d_xl + o) = *(uint2*)l;
}

__global__ void k_splitw(const float* __restrict__ s, __half* __restrict__ hi,
                         __half* __restrict__ lo, int n) {
    int i = blockIdx.x * blockDim.x + threadIdx.x;
    if (i >= n) return;
    float f = s[i];
    __half h = __float2half_rn(f);
    hi[i] = h;
    lo[i] = __float2half_rn(f - __half2float(h));
}

// ---------------- kNN: fp16 HMMA, chunk=32, 2 CTAs/SM, pipelined select -----
#define PB 272
#define TQB (128*PB)
#define TCB (32*PB)
#define SQ 0
#define SC (2*TQB)
#define SCSQ (SC + 4*TCB)
#define SMTOT (SCSQ + 4*32*4)     // csq ring of 4
#define NCH (NN/32)

// parallel sorted-insert: O(1) dependency depth. caller guarantees key < bd[15].
__device__ __forceinline__ void ins16par(float* bd, uint32_t* bi, float key, uint32_t idx) {
    bool c[16];
#pragma unroll
    for (int j = 0; j < 15; j++) c[j] = (bd[j] > key);
    c[15] = true;
#pragma unroll
    for (int j = 15; j > 0; j--) {
        float    nb = c[j-1] ? bd[j-1] : key;
        uint32_t ni = c[j-1] ? bi[j-1] : idx;
        bd[j] = c[j] ? nb : bd[j];
        bi[j] = c[j] ? ni : bi[j];
    }
    bd[0] = c[0] ? key : bd[0];
    bi[0] = c[0] ? idx : bi[0];
}

__global__ __launch_bounds__(256, 2)
void k_knn(const __half* __restrict__ xh, const __half* __restrict__ xl,
           float* __restrict__ esrc, float* __restrict__ edst, int we) {
    extern __shared__ char sm[];
    const uint32_t smb = smem_u32(sm);
    float* csq = (float*)(sm + SCSQ);         // ring of 4 x 32
    const int t = threadIdx.x, w = t >> 5, lane = t & 31;
    const int b = blockIdx.y, qb = blockIdx.x * 128, gbase = b * NN;
    const float FINF = __int_as_float(0x7f800000);
    const __half* xs[2] = {xh, xl};

    // prologue: 2 query split tiles + candidate chunk 0
    for (int s = 0; s < 2; s++) {
        for (int it = t; it < 2048; it += 256) {
            int row = it >> 4, c = it & 15;
            cpa16(smb + SQ + s*TQB + row*PB + c*16,
                  xs[s] + ((size_t)(gbase + qb + row) << 7) + c*8);
        }
        for (int it = t; it < 512; it += 256) {
            int row = it >> 4, c = it & 15;
            cpa16(smb + SC + s*TCB + row*PB + c*16,
                  xs[s] + ((size_t)(gbase + row) << 7) + c*8);
        }
    }
    if (t < 32) csq[t] = d_sqn[gbase + t];
    cp_commit();

    const int q = lane & 3;
    const bool odd = (lane & 1) != 0;
    const int myrow = w * 16 + (lane >> 2) + (odd ? 8 : 0);
    const int qrow = qb + myrow;
    const int lid = q >> 1;
    const uint32_t aoff_base = smb + SQ + (w*16 + (lane & 15))*PB + (lane >> 4)*16;
    const uint32_t bcol = ((lane >> 4)*8 + (lane & 7))*PB + ((lane >> 3) & 1)*16;

    float bd0[16];
    uint32_t bi0[16];
#pragma unroll
    for (int j = 0; j < 16; j++) { bd0[j] = FINF; bi0[j] = 0; }

    float acc[2][4][4];

    // prefetch chunk j (cand tiles into buf j&1, csq into ring slot j&3)
    auto prefetch = [&](int j) {
        const int nb_ = j & 1, cbj = j * 32;
        for (int s = 0; s < 2; s++)
            for (int it = t; it < 512; it += 256) {
                int row = it >> 4, c = it & 15;
                cpa16(smb + SC + (nb_*2 + s)*TCB + row*PB + c*16,
                      xs[s] + ((size_t)(gbase + cbj + row) << 7) + c*8);
            }
        if (t < 32) csq[(j & 3) * 32 + t] = d_sqn[gbase + cbj + t];
        cp_commit();
    };

    // MMA for chunk j into accumulator slot aj
    auto mma_chunk = [&](int j, float (*A)[4]) {
#pragma unroll
        for (int nt = 0; nt < 4; nt++)
#pragma unroll
            for (int v = 0; v < 4; v++) A[nt][v] = 0.f;
        const uint32_t chB = smb + SC + ((j & 1)*2) * TCB + bcol;
#pragma unroll 2
        for (int ks = 0; ks < 8; ks++) {
            uint32_t afh[4], afl[4];
            const uint32_t aaddr = aoff_base + ks*32;
            ldsm4(afh, aaddr);
            ldsm4(afl, aaddr + TQB);
#pragma unroll
            for (int p = 0; p < 2; p++) {
                const uint32_t bbase = chB + p*(16*PB) + ks*32;
                uint32_t bh[4], bl[4];
                ldsm4(bh, bbase);
                ldsm4(bl, bbase + TCB);
                mma16816(A[2*p],     afh, bh);
                mma16816(A[2*p],     afh, bl);
                mma16816(A[2*p],     afl, bh);
                mma16816(A[2*p + 1], afh, bh + 2);
                mma16816(A[2*p + 1], afh, bl + 2);
                mma16816(A[2*p + 1], afl, bh + 2);
            }
        }
    };

    // selection for chunk j from accumulator slot
    auto select_chunk = [&](int j, const float (*A)[4]) {
        const float* cs = csq + (j & 3) * 32;
        const int cb = j * 32;
        const bool diag = (cb >= qb) && (cb < qb + 128);
#pragma unroll
        for (int nt = 0; nt < 4; nt++) {
            const int cl = nt*8 + 2*q;
            const float2 cq = *(const float2*)(cs + cl);
            float k00 = fmaf(-2.f, A[nt][0], cq.x);
            float k01 = fmaf(-2.f, A[nt][1], cq.y);
            float k10 = fmaf(-2.f, A[nt][2], cq.x);
            float k11 = fmaf(-2.f, A[nt][3], cq.y);
            float r0v = __shfl_xor_sync(0xffffffffu, odd ? k00 : k10, 1);
            float r1v = __shfl_xor_sync(0xffffffffu, odd ? k01 : k11, 1);
            float key0 = odd ? r0v : k00;
            float key1 = odd ? r1v : k01;
            float key2 = odd ? k10 : r0v;
            float key3 = odd ? k11 : r1v;
            const int ci = cb + nt*8 + ((q >> 1) << 2);
            if (diag) {
                if (qrow == ci)     key0 = FINF;
                if (qrow == ci + 1) key1 = FINF;
                if (qrow == ci + 2) key2 = FINF;
                if (qrow == ci + 3) key3 = FINF;
            }
            if (fminf(fminf(key0, key1), fminf(key2, key3)) < bd0[15]) {
                if (key0 < bd0[15]) ins16par(bd0, bi0, key0, (uint32_t)ci);
                if (key1 < bd0[15]) ins16par(bd0, bi0, key1, (uint32_t)(ci + 1));
                if (key2 < bd0[15]) ins16par(bd0, bi0, key2, (uint32_t)(ci + 2));
                if (key3 < bd0[15]) ins16par(bd0, bi0, key3, (uint32_t)(ci + 3));
            }
        }
    };

    // iteration 0: MMA chunk 0 (no selection yet)
    cp_wait0();
    __syncthreads();
    prefetch(1);
    mma_chunk(0, acc[0]);

    // pipelined: MMA chunk i overlaps selection of chunk i-1
    for (int i = 1; i < NCH; i++) {
        cp_wait0();
        __syncthreads();
        if (i + 1 < NCH) prefetch(i + 1);
        mma_chunk(i, acc[i & 1]);
        select_chunk(i - 1, acc[(i - 1) & 1]);
    }
    // epilogue: select last chunk
    select_chunk(NCH - 1, acc[(NCH - 1) & 1]);
    __syncthreads();

    // dump lists into the (now dead) query tile area: 2 lists per row
    float* dk = (float*)(sm + SQ);
    int*   di = (int*)(sm + SQ + 32768);
#pragma unroll
    for (int j = 0; j < 16; j++) {
        dk[(myrow*2 + lid)*16 + j] = bd0[j];
        di[(myrow*2 + lid)*16 + j] = (int)bi0[j];
    }
    __syncthreads();

    // 2-way merge per query (lexicographic (key, idx) == top_k tie-break)
    if (t < 128) {
        const float* ka  = dk + t*32;
        const float* kb2 = ka + 16;
        const int*   ia  = di + t*32;
        const int*   ib  = ia + 16;
        int pa = 0, pb = 0;
        int qg = gbase + qb + t;
#pragma unroll 1
        for (int k = 0; k < 16; k++) {
            float kva = ka[pa], kvb = kb2[pb];
            int   iva = ia[pa], ivb = ib[pb];
            bool takeA = (kva < kvb) || (kva == kvb && iva < ivb);
            int sel = takeA ? iva : ivb;
            if (takeA) pa++; else pb++;
            int sg = gbase + sel;
            size_t e = (size_t)qg * KNB + k;
            d_nbr[e] = sg;
            if (we) { esrc[e] = (float)sg; edst[e] = (float)qg; }
        }
    }
}

// ---------------- agg(x): 128-dim fp32 gather, 2 nodes/block ---------------
__global__ __launch_bounds__(256) void k_aggx(const float* __restrict__ x,
                                              __half* __restrict__ oh,
                                              __half* __restrict__ ol) {
    const int node = blockIdx.x * 2 + (threadIdx.x >> 7);
    const int t = threadIdx.x & 127;
    __shared__ int nb_s[2][KNB];
    if (t < KNB) nb_s[threadIdx.x >> 7][t] = d_nbr[(size_t)node * KNB + t];
    __syncthreads();
    const int* nbp = nb_s[threadIdx.x >> 7];
    const float norm = 1.0f / 17.0f;
    float acc = 0.f;
#pragma unroll
    for (int k = 0; k < KNB; k++) acc += x[(size_t)nbp[k] * IND + t] * norm;
    acc += x[(size_t)node * IND + t] * norm;
    __half h = __float2half_rn(acc);
    oh[(size_t)node * IND + t] = h;
    ol[(size_t)node * IND + t] = __float2half_rn(acc - __half2float(h));
}

// ---------------- agg(h1): 256-dim packed gather ----------------------------
__global__ __launch_bounds__(256) void k_aggh(const uint32_t* __restrict__ gp,
                                              __half* __restrict__ oh,
                                              __half* __restrict__ ol) {
    const int node = blockIdx.x;
    const int t = threadIdx.x;
    __shared__ int nb_s[KNB];
    if (t < KNB) nb_s[t] = d_nbr[(size_t)node * KNB + t];
    __syncthreads();
    const float norm = 1.0f / 17.0f;
    float acc = 0.f;
#pragma unroll
    for (int k = 0; k < KNB; k++) {
        uint32_t p = gp[(size_t)nb_s[k] * OUTD + t];
        acc += (__half2float(__ushort_as_half((unsigned short)(p & 0xffff)))
              + __half2float(__ushort_as_half((unsigned short)(p >> 16)))) * norm;
    }
    {
        uint32_t p = gp[(size_t)node * OUTD + t];
        acc += (__half2float(__ushort_as_half((unsigned short)(p & 0xffff)))
              + __half2float(__ushort_as_half((unsigned short)(p >> 16)))) * norm;
    }
    __half h = __float2half_rn(acc);
    oh[(size_t)node * OUTD + t] = h;
    ol[(size_t)node * OUTD + t] = __float2half_rn(acc - __half2float(h));
}

// ---------------- GEMM smem layout ----------------
#define GAP 80
#define GBP 272
#define AH0 0
#define AL0 10240
#define AH1 20480
#define AL1 30720
#define WH0 40960
#define WL0 49664
#define WH1 58368
#define WL1 67072
#define GSM 75776

// ---------------- GEMM1: h1 = relu(ax@W1 + b1) -> packed (h,l) --------------
__global__ __launch_bounds__(256)
void k_gemm1(const __half* __restrict__ Ahi, const __half* __restrict__ Alo,
             const __half* __restrict__ Whi, const __half* __restrict__ Wlo,
             const float* __restrict__ bias, uint32_t* __restrict__ Cp) {
    extern __shared__ char sm[];
    const uint32_t smb = smem_u32(sm);
    const int t = threadIdx.x, w = t >> 5, lane = t & 31;
    const int nbb = blockIdx.x * 128, mb = blockIdx.y * 128;
    const int wm = (w >> 1) * 32, wn = (w & 1) * 64;
    const int Kd = IND, nchunk = IND / 32;

    for (int it = t; it < 512; it += 256) {
        int row = it >> 2, c = it & 3;
        cpa16(smb + AH0 + row*GAP + c*16, Ahi + (size_t)(mb + row)*Kd + c*8);
        cpa16(smb + AL0 + row*GAP + c*16, Alo + (size_t)(mb + row)*Kd + c*8);
    }
    for (int it = t; it < 512; it += 256) {
        int row = it >> 4, c = it & 15;
        cpa16(smb + WH0 + row*GBP + c*16, Whi + (size_t)row*OUTD + nbb + c*8);
        cpa16(smb + WL0 + row*GBP + c*16, Wlo + (size_t)row*OUTD + nbb + c*8);
    }
    cp_commit();

    float acc[2][8][4];
#pragma unroll
    for (int mt = 0; mt < 2; mt++)
#pragma unroll
        for (int nt = 0; nt < 8; nt++)
#pragma unroll
            for (int v = 0; v < 4; v++) acc[mt][nt][v] = 0.f;

    for (int i = 0; i < nchunk; i++) {
        cp_wait0();
        __syncthreads();
        if (i + 1 < nchunk) {
            uint32_t ah = ((i + 1) & 1) ? AH1 : AH0, al = ((i + 1) & 1) ? AL1 : AL0;
            uint32_t wh = ((i + 1) & 1) ? WH1 : WH0, wl = ((i + 1) & 1) ? WL1 : WL0;
            int kc = (i + 1) * 32;
            for (int it = t; it < 512; it += 256) {
                int row = it >> 2, c = it & 3;
                cpa16(smb + ah + row*GAP + c*16, Ahi + (size_t)(mb + row)*Kd + kc + c*8);
                cpa16(smb + al + row*GAP + c*16, Alo + (size_t)(mb + row)*Kd + kc + c*8);
            }
            for (int it = t; it < 512; it += 256) {
                int row = it >> 4, c = it & 15;
                cpa16(smb + wh + row*GBP + c*16, Whi + (size_t)(kc + row)*OUTD + nbb + c*8);
                cpa16(smb + wl + row*GBP + c*16, Wlo + (size_t)(kc + row)*OUTD + nbb + c*8);
            }
            cp_commit();
        }
        const uint32_t ah = smb + ((i & 1) ? AH1 : AH0), al = smb + ((i & 1) ? AL1 : AL0);
        const uint32_t wh = smb + ((i & 1) ? WH1 : WH0), wl = smb + ((i & 1) ? WL1 : WL0);
#pragma unroll
        for (int ks = 0; ks < 2; ks++) {
            uint32_t afh[2][4], afl[2][4];
#pragma unroll
            for (int mt = 0; mt < 2; mt++) {
                uint32_t aoff = (wm + mt*16 + (lane & 15))*GAP + ks*32 + (lane >> 4)*16;
                ldsm4(afh[mt], ah + aoff);
                ldsm4(afl[mt], al + aoff);
            }
#pragma unroll
            for (int nt = 0; nt < 8; nt++) {
                uint32_t boff = (ks*16 + (lane & 15))*GBP + (wn + nt*8)*2;
                uint32_t bfh[2], bfl[2];
                ldsm2t(bfh, wh + boff);
                ldsm2t(bfl, wl + boff);
#pragma unroll
                for (int mt = 0; mt < 2; mt++) {
                    mma16816(acc[mt][nt], afh[mt], bfh);
                    mma16816(acc[mt][nt], afh[mt], bfl);
                    mma16816(acc[mt][nt], afl[mt], bfh);
                }
            }
        }
    }
#pragma unroll
    for (int mt = 0; mt < 2; mt++) {
#pragma unroll
        for (int nt = 0; nt < 8; nt++) {
            int m0 = mb + wm + mt*16 + (lane >> 2);
            int n0 = nbb + wn + nt*8 + 2*(lane & 3);
            float b0 = bias[n0], b1v = bias[n0 + 1];
#pragma unroll
            for (int rr = 0; rr < 2; rr++) {
                int m = m0 + rr * 8;
                float v0 = fmaxf(acc[mt][nt][rr*2 + 0] + b0, 0.f);
                float v1 = fmaxf(acc[mt][nt][rr*2 + 1] + b1v, 0.f);
                __half h0 = __float2half_rn(v0), h1 = __float2half_rn(v1);
                __half l0 = __float2half_rn(v0 - __half2float(h0));
                __half l1 = __float2half_rn(v1 - __half2float(h1));
                uint2 pk;
                pk.x = (uint32_t)__half_as_ushort(h0) | ((uint32_t)__half_as_ushort(l0) << 16);
                pk.y = (uint32_t)__half_as_ushort(h1) | ((uint32_t)__half_as_ushort(l1) << 16);
                *(uint2*)(Cp + (size_t)m * OUTD + n0) = pk;
            }
        }
    }
}

// ---------------- GEMM2: out = ah@W2 + x@Ws + (b2+bs) -----------------------
__global__ __launch_bounds__(256)
void k_gemm2(const __half* __restrict__ A1h, const __half* __restrict__ A1l,
             const __half* __restrict__ W1h_, const __half* __restrict__ W1l_,
             const __half* __restrict__ A2h, const __half* __restrict__ A2l,
             const __half* __restrict__ W2h_, const __half* __restrict__ W2l_,
             const float* __restrict__ bias1, const float* __restrict__ bias2,
             float* __restrict__ C) {
    extern __shared__ char sm[];
    const uint32_t smb = smem_u32(sm);
    const int t = threadIdx.x, w = t >> 5, lane = t & 31;
    const int nbb = blockIdx.x * 128, mb = blockIdx.y * 128;
    const int wm = (w >> 1) * 32, wn = (w & 1) * 64;
    const int NC1 = OUTD / 32;
    const int NC = NC1 + IND / 32;

    auto prefetch = [&](int j, int pb) {
        uint32_t ah = pb ? AH1 : AH0, al = pb ? AL1 : AL0;
        uint32_t wh = pb ? WH1 : WH0, wl = pb ? WL1 : WL0;
        const __half *Ah, *Al, *Wh, *Wl;
        int Kd, kc;
        if (j < NC1) { Ah = A1h; Al = A1l; Wh = W1h_; Wl = W1l_; Kd = OUTD; kc = j * 32; }
        else         { Ah = A2h; Al = A2l; Wh = W2h_; Wl = W2l_; Kd = IND;  kc = (j - NC1) * 32; }
        for (int it = t; it < 512; it += 256) {
            int row = it >> 2, c = it & 3;
            cpa16(smb + ah + row*GAP + c*16, Ah + (size_t)(mb + row)*Kd + kc + c*8);
            cpa16(smb + al + row*GAP + c*16, Al + (size_t)(mb + row)*Kd + kc + c*8);
        }
        for (int it = t; it < 512; it += 256) {
            int row = it >> 4, c = it & 15;
            cpa16(smb + wh + row*GBP + c*16, Wh + (size_t)(kc + row)*OUTD + nbb + c*8);
            cpa16(smb + wl + row*GBP + c*16, Wl + (size_t)(kc + row)*OUTD + nbb + c*8);
        }
        cp_commit();
    };

    prefetch(0, 0);

    float acc[2][8][4];
#pragma unroll
    for (int mt = 0; mt < 2; mt++)
#pragma unroll
        for (int nt = 0; nt < 8; nt++)
#pragma unroll
            for (int v = 0; v < 4; v++) acc[mt][nt][v] = 0.f;

    for (int i = 0; i < NC; i++) {
        cp_wait0();
        __syncthreads();
        if (i + 1 < NC) prefetch(i + 1, (i + 1) & 1);
        const uint32_t ah = smb + ((i & 1) ? AH1 : AH0), al = smb + ((i & 1) ? AL1 : AL0);
        const uint32_t wh = smb + ((i & 1) ? WH1 : WH0), wl = smb + ((i & 1) ? WL1 : WL0);
#pragma unroll
        for (int ks = 0; ks < 2; ks++) {
            uint32_t afh[2][4], afl[2][4];
#pragma unroll
            for (int mt = 0; mt < 2; mt++) {
                uint32_t aoff = (wm + mt*16 + (lane & 15))*GAP + ks*32 + (lane >> 4)*16;
                ldsm4(afh[mt], ah + aoff);
                ldsm4(afl[mt], al + aoff);
            }
#pragma unroll
            for (int nt = 0; nt < 8; nt++) {
                uint32_t boff = (ks*16 + (lane & 15))*GBP + (wn + nt*8)*2;
                uint32_t bfh[2], bfl[2];
                ldsm2t(bfh, wh + boff);
                ldsm2t(bfl, wl + boff);
#pragma unroll
                for (int mt = 0; mt < 2; mt++) {
                    mma16816(acc[mt][nt], afh[mt], bfh);
                    mma16816(acc[mt][nt], afh[mt], bfl);
                    mma16816(acc[mt][nt], afl[mt], bfh);
                }
            }
        }
    }
#pragma unroll
    for (int mt = 0; mt < 2; mt++) {
#pragma unroll
        for (int nt = 0; nt < 8; nt++) {
            int m0 = mb + wm + mt*16 + (lane >> 2);
            int n0 = nbb + wn + nt*8 + 2*(lane & 3);
            float b0 = bias1[n0] + bias2[n0];
            float b1v = bias1[n0 + 1] + bias2[n0 + 1];
            float2 v0 = make_float2(acc[mt][nt][0] + b0, acc[mt][nt][1] + b1v);
            float2 v1 = make_float2(acc[mt][nt][2] + b0, acc[mt][nt][3] + b1v);
            *(float2*)(C + (size_t)m0 * OUTD + n0) = v0;
            *(float2*)(C + (size_t)(m0 + 8) * OUTD + n0) = v1;
        }
    }
}

// ---------------- launch ----------------
extern "C" void kernel_launch(void* const* d_in, const int* in_sizes, int n_in,
                              void* d_out, int out_size) {
    const float* x  = (const float*)d_in[0];
    const float* W1 = (const float*)d_in[2];
    const float* b1 = (const float*)d_in[3];
    const float* W2 = (const float*)d_in[4];
    const float* b2 = (const float*)d_in[5];
    const float* Ws = (const float*)d_in[6];
    const float* bs = (const float*)d_in[7];

    float* out  = (float*)d_out;
    float* esrc = out + (size_t)NTOT * OUTD;
    float* edst = esrc + NEDGE;
    int we = (out_size >= (int)((size_t)NTOT * OUTD + 2 * NEDGE)) ? 1 : 0;

    __half *xh, *xl, *axh, *axl, *ahh, *ahl;
    uint32_t *h1p;
    __half *w1h, *w1l, *w2h, *w2l, *wsh, *wsl;
    cudaGetSymbolAddress((void**)&xh, d_xh);
    cudaGetSymbolAddress((void**)&xl, d_xl);
    cudaGetSymbolAddress((void**)&axh, d_axh);
    cudaGetSymbolAddress((void**)&axl, d_axl);
    cudaGetSymbolAddress((void**)&h1p, d_h1p);
    cudaGetSymbolAddress((void**)&ahh, d_ahh);
    cudaGetSymbolAddress((void**)&ahl, d_ahl);
    cudaGetSymbolAddress((void**)&w1h, d_w1h);
    cudaGetSymbolAddress((void**)&w1l, d_w1l);
    cudaGetSymbolAddress((void**)&w2h, d_w2h);
    cudaGetSymbolAddress((void**)&w2l, d_w2l);
    cudaGetSymbolAddress((void**)&wsh, d_wsh);
    cudaGetSymbolAddress((void**)&wsl, d_wsl);

    cudaFuncSetAttribute(k_knn, cudaFuncAttributeMaxDynamicSharedMemorySize, SMTOT);
    cudaFuncSetAttribute(k_gemm1, cudaFuncAttributeMaxDynamicSharedMemorySize, GSM);
    cudaFuncSetAttribute(k_gemm2, cudaFuncAttributeMaxDynamicSharedMemorySize, GSM);

    // launch order: k_knn at index 3 (ncu captures launch #3)
    k_prep<<<NTOT / 8, 256>>>(x);                                            // 0
    k_splitw<<<(IND * OUTD + 255) / 256, 256>>>(W1, w1h, w1l, IND * OUTD);   // 1
    k_splitw<<<(IND * OUTD + 255) / 256, 256>>>(Ws, wsh, wsl, IND * OUTD);   // 2
    k_knn<<<dim3(NN / 128, NB), 256, SMTOT>>>(xh, xl, esrc, edst, we);       // 3
    k_splitw<<<(OUTD * OUTD + 255) / 256, 256>>>(W2, w2h, w2l, OUTD * OUTD); // 4
    k_aggx<<<NTOT / 2, 256>>>(x, axh, axl);                                  // 5
    k_gemm1<<<dim3(OUTD / 128, NTOT / 128), 256, GSM>>>(axh, axl, w1h, w1l, b1, h1p); // 6
    k_aggh<<<NTOT, 256>>>(h1p, ahh, ahl);                                    // 7
    k_gemm2<<<dim3(OUTD / 128, NTOT / 128), 256, GSM>>>(ahh, ahl, w2h, w2l,
                                                        xh, xl, wsh, wsl,
                                                        b2, bs, out);        // 8
}

// round 15
// speedup vs baseline: 1.1556x; 1.1556x over previous
#include <cuda_runtime.h>
#include <cuda_fp16.h>
#include <stdint.h>

#define NB 16
#define NN 2048
#define NTOT (NB*NN)
#define KNB 16
#define IND 128
#define OUTD 256
#define NEDGE (NTOT*KNB)

// ---------------- scratch ----------------
__device__ float d_sqn[NTOT];
__device__ int   d_nbr[NTOT*KNB];
__device__ __half d_xh[(size_t)NTOT*IND];
__device__ __half d_xl[(size_t)NTOT*IND];
__device__ __half d_axh[(size_t)NTOT*IND];
__device__ __half d_axl[(size_t)NTOT*IND];
__device__ uint32_t d_h1p[(size_t)NTOT*OUTD];
__device__ __half d_ahh[(size_t)NTOT*OUTD];
__device__ __half d_ahl[(size_t)NTOT*OUTD];
__device__ __half d_w1h[IND*OUTD],  d_w1l[IND*OUTD];
__device__ __half d_w2h[OUTD*OUTD], d_w2l[OUTD*OUTD];
__device__ __half d_wsh[IND*OUTD],  d_wsl[IND*OUTD];

// ---------------- helpers ----------------
__device__ __forceinline__ uint32_t smem_u32(const void* p) {
    uint32_t a;
    asm("{ .reg .u64 t; cvta.to.shared.u64 t, %1; cvt.u32.u64 %0, t; }" : "=r"(a) : "l"(p));
    return a;
}
__device__ __forceinline__ void cpa16(uint32_t dst, const void* src) {
    asm volatile("cp.async.cg.shared.global [%0], [%1], 16;" :: "r"(dst), "l"(src));
}
__device__ __forceinline__ void cp_commit() { asm volatile("cp.async.commit_group;"); }
__device__ __forceinline__ void cp_wait0()  { asm volatile("cp.async.wait_group 0;"); }
__device__ __forceinline__ void ldsm4(uint32_t* r, uint32_t a) {
    asm volatile("ldmatrix.sync.aligned.m8n8.x4.shared.b16 {%0,%1,%2,%3}, [%4];"
        : "=r"(r[0]), "=r"(r[1]), "=r"(r[2]), "=r"(r[3]) : "r"(a));
}
__device__ __forceinline__ void ldsm2t(uint32_t* r, uint32_t a) {
    asm volatile("ldmatrix.sync.aligned.m8n8.x2.trans.shared.b16 {%0,%1}, [%2];"
        : "=r"(r[0]), "=r"(r[1]) : "r"(a));
}
__device__ __forceinline__ void mma16816(float* c, const uint32_t* a, const uint32_t* b) {
    asm volatile("mma.sync.aligned.m16n8k16.row.col.f32.f16.f16.f32 "
        "{%0,%1,%2,%3}, {%4,%5,%6,%7}, {%8,%9}, {%0,%1,%2,%3};"
        : "+f"(c[0]), "+f"(c[1]), "+f"(c[2]), "+f"(c[3])
        : "r"(a[0]), "r"(a[1]), "r"(a[2]), "r"(a[3]), "r"(b[0]), "r"(b[1]));
}

// ---------------- prep: sqn + 2-way fp16 split of x ----------------
__global__ __launch_bounds__(256) void k_prep(const float* __restrict__ x) {
    const int row = blockIdx.x * 8 + (threadIdx.x >> 5);
    const int lane = threadIdx.x & 31;
    float4 v = *(const float4*)(x + (size_t)row * IND + lane * 4);
    float s = v.x*v.x + v.y*v.y + v.z*v.z + v.w*v.w;
#pragma unroll
    for (int o = 16; o > 0; o >>= 1) s += __shfl_xor_sync(0xffffffffu, s, o);
    if (lane == 0) d_sqn[row] = s;
    float f[4] = {v.x, v.y, v.z, v.w};
    __half h[4], l[4];
#pragma unroll
    for (int j = 0; j < 4; j++) {
        h[j] = __float2half_rn(f[j]);
        l[j] = __float2half_rn(f[j] - __half2float(h[j]));
    }
    const size_t o = (size_t)row * IND + lane * 4;
    *(uint2*)(d_xh + o) = *(uint2*)h;
    *(uint2*)(d_xl + o) = *(uint2*)l;
}

__global__ void k_splitw(const float* __restrict__ s, __half* __restrict__ hi,
                         __half* __restrict__ lo, int n) {
    int i = blockIdx.x * blockDim.x + threadIdx.x;
    if (i >= n) return;
    float f = s[i];
    __half h = __float2half_rn(f);
    hi[i] = h;
    lo[i] = __float2half_rn(f - __half2float(h));
}

// ---------------- kNN: fp16 HMMA, chunk=32, 2 CTAs/SM, half-chunk pipeline --
#define PB 272
#define TQB (128*PB)
#define TCB (32*PB)
#define SQ 0
#define SC (2*TQB)
#define SCSQ (SC + 4*TCB)
#define SMTOT (SCSQ + 4*32*4)     // csq ring of 4
#define NCH (NN/32)

// parallel sorted-insert: O(1) dependency depth. caller guarantees key < bd[15].
__device__ __forceinline__ void ins16par(float* bd, uint32_t* bi, float key, uint32_t idx) {
    bool c[16];
#pragma unroll
    for (int j = 0; j < 15; j++) c[j] = (bd[j] > key);
    c[15] = true;
#pragma unroll
    for (int j = 15; j > 0; j--) {
        float    nb = c[j-1] ? bd[j-1] : key;
        uint32_t ni = c[j-1] ? bi[j-1] : idx;
        bd[j] = c[j] ? nb : bd[j];
        bi[j] = c[j] ? ni : bi[j];
    }
    bd[0] = c[0] ? key : bd[0];
    bi[0] = c[0] ? idx : bi[0];
}

__global__ __launch_bounds__(256, 2)
void k_knn(const __half* __restrict__ xh, const __half* __restrict__ xl,
           float* __restrict__ esrc, float* __restrict__ edst, int we) {
    extern __shared__ char sm[];
    const uint32_t smb = smem_u32(sm);
    float* csq = (float*)(sm + SCSQ);         // ring of 4 x 32
    const int t = threadIdx.x, w = t >> 5, lane = t & 31;
    const int b = blockIdx.y, qb = blockIdx.x * 128, gbase = b * NN;
    const float FINF = __int_as_float(0x7f800000);
    const __half* xs[2] = {xh, xl};

    // prologue: 2 query split tiles + candidate chunk 0
    for (int s = 0; s < 2; s++) {
        for (int it = t; it < 2048; it += 256) {
            int row = it >> 4, c = it & 15;
            cpa16(smb + SQ + s*TQB + row*PB + c*16,
                  xs[s] + ((size_t)(gbase + qb + row) << 7) + c*8);
        }
        for (int it = t; it < 512; it += 256) {
            int row = it >> 4, c = it & 15;
            cpa16(smb + SC + s*TCB + row*PB + c*16,
                  xs[s] + ((size_t)(gbase + row) << 7) + c*8);
        }
    }
    if (t < 32) csq[t] = d_sqn[gbase + t];
    cp_commit();

    const int q = lane & 3;
    const bool odd = (lane & 1) != 0;
    const int myrow = w * 16 + (lane >> 2) + (odd ? 8 : 0);
    const int qrow = qb + myrow;
    const int lid = q >> 1;
    const uint32_t aoff_base = smb + SQ + (w*16 + (lane & 15))*PB + (lane >> 4)*16;
    const uint32_t bcol = ((lane >> 4)*8 + (lane & 7))*PB + ((lane >> 3) & 1)*16;

    float bd0[16];
    uint32_t bi0[16];
#pragma unroll
    for (int j = 0; j < 16; j++) { bd0[j] = FINF; bi0[j] = 0; }

    float accA[2][4], accB[2][4];

    // prefetch chunk j (cand tiles into buf j&1, csq into ring slot j&3)
    auto prefetch = [&](int j) {
        const int nb_ = j & 1, cbj = j * 32;
        for (int s = 0; s < 2; s++)
            for (int it = t; it < 512; it += 256) {
                int row = it >> 4, c = it & 15;
                cpa16(smb + SC + (nb_*2 + s)*TCB + row*PB + c*16,
                      xs[s] + ((size_t)(gbase + cbj + row) << 7) + c*8);
            }
        if (t < 32) csq[(j & 3) * 32 + t] = d_sqn[gbase + cbj + t];
        cp_commit();
    };

    // MMA for half p (cands [p*16, p*16+16)) of chunk j into 2x4 accumulator
    auto mma_half = [&](int j, int p, float (*A)[4]) {
#pragma unroll
        for (int nt = 0; nt < 2; nt++)
#pragma unroll
            for (int v = 0; v < 4; v++) A[nt][v] = 0.f;
        const uint32_t chB = smb + SC + ((j & 1)*2) * TCB + bcol + p*(16*PB);
#pragma unroll 2
        for (int ks = 0; ks < 8; ks++) {
            uint32_t afh[4], afl[4];
            const uint32_t aaddr = aoff_base + ks*32;
            ldsm4(afh, aaddr);
            ldsm4(afl, aaddr + TQB);
            const uint32_t bbase = chB + ks*32;
            uint32_t bh[4], bl[4];
            ldsm4(bh, bbase);
            ldsm4(bl, bbase + TCB);
            mma16816(A[0], afh, bh);
            mma16816(A[0], afh, bl);
            mma16816(A[0], afl, bh);
            mma16816(A[1], afh, bh + 2);
            mma16816(A[1], afh, bl + 2);
            mma16816(A[1], afl, bh + 2);
        }
    };

    // selection for half p of chunk j
    auto select_half = [&](int j, int p, const float (*A)[4]) {
        const float* cs = csq + (j & 3) * 32;
        const int cb = j * 32;
        const bool diag = (cb >= qb) && (cb < qb + 128);
#pragma unroll
        for (int nt2 = 0; nt2 < 2; nt2++) {
            const int nt = p*2 + nt2;
            const int cl = nt*8 + 2*q;
            const float2 cq = *(const float2*)(cs + cl);
            float k00 = fmaf(-2.f, A[nt2][0], cq.x);
            float k01 = fmaf(-2.f, A[nt2][1], cq.y);
            float k10 = fmaf(-2.f, A[nt2][2], cq.x);
            float k11 = fmaf(-2.f, A[nt2][3], cq.y);
            float r0v = __shfl_xor_sync(0xffffffffu, odd ? k00 : k10, 1);
            float r1v = __shfl_xor_sync(0xffffffffu, odd ? k01 : k11, 1);
            float key0 = odd ? r0v : k00;
            float key1 = odd ? r1v : k01;
            float key2 = odd ? k10 : r0v;
            float key3 = odd ? k11 : r1v;
            const int ci = cb + nt*8 + ((q >> 1) << 2);
            if (diag) {
                if (qrow == ci)     key0 = FINF;
                if (qrow == ci + 1) key1 = FINF;
                if (qrow == ci + 2) key2 = FINF;
                if (qrow == ci + 3) key3 = FINF;
            }
            if (fminf(fminf(key0, key1), fminf(key2, key3)) < bd0[15]) {
                if (key0 < bd0[15]) ins16par(bd0, bi0, key0, (uint32_t)ci);
                if (key1 < bd0[15]) ins16par(bd0, bi0, key1, (uint32_t)(ci + 1));
                if (key2 < bd0[15]) ins16par(bd0, bi0, key2, (uint32_t)(ci + 2));
                if (key3 < bd0[15]) ins16par(bd0, bi0, key3, (uint32_t)(ci + 3));
            }
        }
    };

    // half-chunk software pipeline:
    //   iter i: mma h0(i) | select h1(i-1) | mma h1(i) | select h0(i)
    for (int i = 0; i < NCH; i++) {
        cp_wait0();
        __syncthreads();
        if (i + 1 < NCH) prefetch(i + 1);
        mma_half(i, 0, accA);
        if (i > 0) select_half(i - 1, 1, accB);
        mma_half(i, 1, accB);
        select_half(i, 0, accA);
    }
    select_half(NCH - 1, 1, accB);
    __syncthreads();

    // dump lists into the (now dead) query tile area: 2 lists per row
    float* dk = (float*)(sm + SQ);
    int*   di = (int*)(sm + SQ + 32768);
#pragma unroll
    for (int j = 0; j < 16; j++) {
        dk[(myrow*2 + lid)*16 + j] = bd0[j];
        di[(myrow*2 + lid)*16 + j] = (int)bi0[j];
    }
    __syncthreads();

    // 2-way merge per query (lexicographic (key, idx) == top_k tie-break)
    if (t < 128) {
        const float* ka  = dk + t*32;
        const float* kb2 = ka + 16;
        const int*   ia  = di + t*32;
        const int*   ib  = ia + 16;
        int pa = 0, pb = 0;
        int qg = gbase + qb + t;
#pragma unroll 1
        for (int k = 0; k < 16; k++) {
            float kva = ka[pa], kvb = kb2[pb];
            int   iva = ia[pa], ivb = ib[pb];
            bool takeA = (kva < kvb) || (kva == kvb && iva < ivb);
            int sel = takeA ? iva : ivb;
            if (takeA) pa++; else pb++;
            int sg = gbase + sel;
            size_t e = (size_t)qg * KNB + k;
            d_nbr[e] = sg;
            if (we) { esrc[e] = (float)sg; edst[e] = (float)qg; }
        }
    }
}

// ---------------- agg(x): 128-dim fp32 gather, 2 nodes/block ---------------
__global__ __launch_bounds__(256) void k_aggx(const float* __restrict__ x,
                                              __half* __restrict__ oh,
                                              __half* __restrict__ ol) {
    const int node = blockIdx.x * 2 + (threadIdx.x >> 7);
    const int t = threadIdx.x & 127;
    __shared__ int nb_s[2][KNB];
    if (t < KNB) nb_s[threadIdx.x >> 7][t] = d_nbr[(size_t)node * KNB + t];
    __syncthreads();
    const int* nbp = nb_s[threadIdx.x >> 7];
    const float norm = 1.0f / 17.0f;
    float acc = 0.f;
#pragma unroll
    for (int k = 0; k < KNB; k++) acc += x[(size_t)nbp[k] * IND + t] * norm;
    acc += x[(size_t)node * IND + t] * norm;
    __half h = __float2half_rn(acc);
    oh[(size_t)node * IND + t] = h;
    ol[(size_t)node * IND + t] = __float2half_rn(acc - __half2float(h));
}

// ---------------- agg(h1): 256-dim packed gather ----------------------------
__global__ __launch_bounds__(256) void k_aggh(const uint32_t* __restrict__ gp,
                                              __half* __restrict__ oh,
                                              __half* __restrict__ ol) {
    const int node = blockIdx.x;
    const int t = threadIdx.x;
    __shared__ int nb_s[KNB];
    if (t < KNB) nb_s[t] = d_nbr[(size_t)node * KNB + t];
    __syncthreads();
    const float norm = 1.0f / 17.0f;
    float acc = 0.f;
#pragma unroll
    for (int k = 0; k < KNB; k++) {
        uint32_t p = gp[(size_t)nb_s[k] * OUTD + t];
        acc += (__half2float(__ushort_as_half((unsigned short)(p & 0xffff)))
              + __half2float(__ushort_as_half((unsigned short)(p >> 16)))) * norm;
    }
    {
        uint32_t p = gp[(size_t)node * OUTD + t];
        acc += (__half2float(__ushort_as_half((unsigned short)(p & 0xffff)))
              + __half2float(__ushort_as_half((unsigned short)(p >> 16)))) * norm;
    }
    __half h = __float2half_rn(acc);
    oh[(size_t)node * OUTD + t] = h;
    ol[(size_t)node * OUTD + t] = __float2half_rn(acc - __half2float(h));
}

// ---------------- GEMM smem layout ----------------
#define GAP 80
#define GBP 272
#define AH0 0
#define AL0 10240
#define AH1 20480
#define AL1 30720
#define WH0 40960
#define WL0 49664
#define WH1 58368
#define WL1 67072
#define GSM 75776

// ---------------- GEMM1: h1 = relu(ax@W1 + b1) -> packed (h,l) --------------
__global__ __launch_bounds__(256)
void k_gemm1(const __half* __restrict__ Ahi, const __half* __restrict__ Alo,
             const __half* __restrict__ Whi, const __half* __restrict__ Wlo,
             const float* __restrict__ bias, uint32_t* __restrict__ Cp) {
    extern __shared__ char sm[];
    const uint32_t smb = smem_u32(sm);
    const int t = threadIdx.x, w = t >> 5, lane = t & 31;
    const int nbb = blockIdx.x * 128, mb = blockIdx.y * 128;
    const int wm = (w >> 1) * 32, wn = (w & 1) * 64;
    const int Kd = IND, nchunk = IND / 32;

    for (int it = t; it < 512; it += 256) {
        int row = it >> 2, c = it & 3;
        cpa16(smb + AH0 + row*GAP + c*16, Ahi + (size_t)(mb + row)*Kd + c*8);
        cpa16(smb + AL0 + row*GAP + c*16, Alo + (size_t)(mb + row)*Kd + c*8);
    }
    for (int it = t; it < 512; it += 256) {
        int row = it >> 4, c = it & 15;
        cpa16(smb + WH0 + row*GBP + c*16, Whi + (size_t)row*OUTD + nbb + c*8);
        cpa16(smb + WL0 + row*GBP + c*16, Wlo + (size_t)row*OUTD + nbb + c*8);
    }
    cp_commit();

    float acc[2][8][4];
#pragma unroll
    for (int mt = 0; mt < 2; mt++)
#pragma unroll
        for (int nt = 0; nt < 8; nt++)
#pragma unroll
            for (int v = 0; v < 4; v++) acc[mt][nt][v] = 0.f;

    for (int i = 0; i < nchunk; i++) {
        cp_wait0();
        __syncthreads();
        if (i + 1 < nchunk) {
            uint32_t ah = ((i + 1) & 1) ? AH1 : AH0, al = ((i + 1) & 1) ? AL1 : AL0;
            uint32_t wh = ((i + 1) & 1) ? WH1 : WH0, wl = ((i + 1) & 1) ? WL1 : WL0;
            int kc = (i + 1) * 32;
            for (int it = t; it < 512; it += 256) {
                int row = it >> 2, c = it & 3;
                cpa16(smb + ah + row*GAP + c*16, Ahi + (size_t)(mb + row)*Kd + kc + c*8);
                cpa16(smb + al + row*GAP + c*16, Alo + (size_t)(mb + row)*Kd + kc + c*8);
            }
            for (int it = t; it < 512; it += 256) {
                int row = it >> 4, c = it & 15;
                cpa16(smb + wh + row*GBP + c*16, Whi + (size_t)(kc + row)*OUTD + nbb + c*8);
                cpa16(smb + wl + row*GBP + c*16, Wlo + (size_t)(kc + row)*OUTD + nbb + c*8);
            }
            cp_commit();
        }
        const uint32_t ah = smb + ((i & 1) ? AH1 : AH0), al = smb + ((i & 1) ? AL1 : AL0);
        const uint32_t wh = smb + ((i & 1) ? WH1 : WH0), wl = smb + ((i & 1) ? WL1 : WL0);
#pragma unroll
        for (int ks = 0; ks < 2; ks++) {
            uint32_t afh[2][4], afl[2][4];
#pragma unroll
            for (int mt = 0; mt < 2; mt++) {
                uint32_t aoff = (wm + mt*16 + (lane & 15))*GAP + ks*32 + (lane >> 4)*16;
                ldsm4(afh[mt], ah + aoff);
                ldsm4(afl[mt], al + aoff);
            }
#pragma unroll
            for (int nt = 0; nt < 8; nt++) {
                uint32_t boff = (ks*16 + (lane & 15))*GBP + (wn + nt*8)*2;
                uint32_t bfh[2], bfl[2];
                ldsm2t(bfh, wh + boff);
                ldsm2t(bfl, wl + boff);
#pragma unroll
                for (int mt = 0; mt < 2; mt++) {
                    mma16816(acc[mt][nt], afh[mt], bfh);
                    mma16816(acc[mt][nt], afh[mt], bfl);
                    mma16816(acc[mt][nt], afl[mt], bfh);
                }
            }
        }
    }
#pragma unroll
    for (int mt = 0; mt < 2; mt++) {
#pragma unroll
        for (int nt = 0; nt < 8; nt++) {
            int m0 = mb + wm + mt*16 + (lane >> 2);
            int n0 = nbb + wn + nt*8 + 2*(lane & 3);
            float b0 = bias[n0], b1v = bias[n0 + 1];
#pragma unroll
            for (int rr = 0; rr < 2; rr++) {
                int m = m0 + rr * 8;
                float v0 = fmaxf(acc[mt][nt][rr*2 + 0] + b0, 0.f);
                float v1 = fmaxf(acc[mt][nt][rr*2 + 1] + b1v, 0.f);
                __half h0 = __float2half_rn(v0), h1 = __float2half_rn(v1);
                __half l0 = __float2half_rn(v0 - __half2float(h0));
                __half l1 = __float2half_rn(v1 - __half2float(h1));
                uint2 pk;
                pk.x = (uint32_t)__half_as_ushort(h0) | ((uint32_t)__half_as_ushort(l0) << 16);
                pk.y = (uint32_t)__half_as_ushort(h1) | ((uint32_t)__half_as_ushort(l1) << 16);
                *(uint2*)(Cp + (size_t)m * OUTD + n0) = pk;
            }
        }
    }
}

// ---------------- GEMM2: out = ah@W2 + x@Ws + (b2+bs) -----------------------
__global__ __launch_bounds__(256)
void k_gemm2(const __half* __restrict__ A1h, const __half* __restrict__ A1l,
             const __half* __restrict__ W1h_, const __half* __restrict__ W1l_,
             const __half* __restrict__ A2h, const __half* __restrict__ A2l,
             const __half* __restrict__ W2h_, const __half* __restrict__ W2l_,
             const float* __restrict__ bias1, const float* __restrict__ bias2,
             float* __restrict__ C) {
    extern __shared__ char sm[];
    const uint32_t smb = smem_u32(sm);
    const int t = threadIdx.x, w = t >> 5, lane = t & 31;
    const int nbb = blockIdx.x * 128, mb = blockIdx.y * 128;
    const int wm = (w >> 1) * 32, wn = (w & 1) * 64;
    const int NC1 = OUTD / 32;
    const int NC = NC1 + IND / 32;

    auto prefetch = [&](int j, int pb) {
        uint32_t ah = pb ? AH1 : AH0, al = pb ? AL1 : AL0;
        uint32_t wh = pb ? WH1 : WH0, wl = pb ? WL1 : WL0;
        const __half *Ah, *Al, *Wh, *Wl;
        int Kd, kc;
        if (j < NC1) { Ah = A1h; Al = A1l; Wh = W1h_; Wl = W1l_; Kd = OUTD; kc = j * 32; }
        else         { Ah = A2h; Al = A2l; Wh = W2h_; Wl = W2l_; Kd = IND;  kc = (j - NC1) * 32; }
        for (int it = t; it < 512; it += 256) {
            int row = it >> 2, c = it & 3;
            cpa16(smb + ah + row*GAP + c*16, Ah + (size_t)(mb + row)*Kd + kc + c*8);
            cpa16(smb + al + row*GAP + c*16, Al + (size_t)(mb + row)*Kd + kc + c*8);
        }
        for (int it = t; it < 512; it += 256) {
            int row = it >> 4, c = it & 15;
            cpa16(smb + wh + row*GBP + c*16, Wh + (size_t)(kc + row)*OUTD + nbb + c*8);
            cpa16(smb + wl + row*GBP + c*16, Wl + (size_t)(kc + row)*OUTD + nbb + c*8);
        }
        cp_commit();
    };

    prefetch(0, 0);

    float acc[2][8][4];
#pragma unroll
    for (int mt = 0; mt < 2; mt++)
#pragma unroll
        for (int nt = 0; nt < 8; nt++)
#pragma unroll
            for (int v = 0; v < 4; v++) acc[mt][nt][v] = 0.f;

    for (int i = 0; i < NC; i++) {
        cp_wait0();
        __syncthreads();
        if (i + 1 < NC) prefetch(i + 1, (i + 1) & 1);
        const uint32_t ah = smb + ((i & 1) ? AH1 : AH0), al = smb + ((i & 1) ? AL1 : AL0);
        const uint32_t wh = smb + ((i & 1) ? WH1 : WH0), wl = smb + ((i & 1) ? WL1 : WL0);
#pragma unroll
        for (int ks = 0; ks < 2; ks++) {
            uint32_t afh[2][4], afl[2][4];
#pragma unroll
            for (int mt = 0; mt < 2; mt++) {
                uint32_t aoff = (wm + mt*16 + (lane & 15))*GAP + ks*32 + (lane >> 4)*16;
                ldsm4(afh[mt], ah + aoff);
                ldsm4(afl[mt], al + aoff);
            }
#pragma unroll
            for (int nt = 0; nt < 8; nt++) {
                uint32_t boff = (ks*16 + (lane & 15))*GBP + (wn + nt*8)*2;
                uint32_t bfh[2], bfl[2];
                ldsm2t(bfh, wh + boff);
                ldsm2t(bfl, wl + boff);
#pragma unroll
                for (int mt = 0; mt < 2; mt++) {
                    mma16816(acc[mt][nt], afh[mt], bfh);
                    mma16816(acc[mt][nt], afh[mt], bfl);
                    mma16816(acc[mt][nt], afl[mt], bfh);
                }
            }
        }
    }
#pragma unroll
    for (int mt = 0; mt < 2; mt++) {
#pragma unroll
        for (int nt = 0; nt < 8; nt++) {
            int m0 = mb + wm + mt*16 + (lane >> 2);
            int n0 = nbb + wn + nt*8 + 2*(lane & 3);
            float b0 = bias1[n0] + bias2[n0];
            float b1v = bias1[n0 + 1] + bias2[n0 + 1];
            float2 v0 = make_float2(acc[mt][nt][0] + b0, acc[mt][nt][1] + b1v);
            float2 v1 = make_float2(acc[mt][nt][2] + b0, acc[mt][nt][3] + b1v);
            *(float2*)(C + (size_t)m0 * OUTD + n0) = v0;
            *(float2*)(C + (size_t)(m0 + 8) * OUTD + n0) = v1;
        }
    }
}

// ---------------- launch ----------------
extern "C" void kernel_launch(void* const* d_in, const int* in_sizes, int n_in,
                              void* d_out, int out_size) {
    const float* x  = (const float*)d_in[0];
    const float* W1 = (const float*)d_in[2];
    const float* b1 = (const float*)d_in[3];
    const float* W2 = (const float*)d_in[4];
    const float* b2 = (const float*)d_in[5];
    const float* Ws = (const float*)d_in[6];
    const float* bs = (const float*)d_in[7];

    float* out  = (float*)d_out;
    float* esrc = out + (size_t)NTOT * OUTD;
    float* edst = esrc + NEDGE;
    int we = (out_size >= (int)((size_t)NTOT * OUTD + 2 * NEDGE)) ? 1 : 0;

    __half *xh, *xl, *axh, *axl, *ahh, *ahl;
    uint32_t *h1p;
    __half *w1h, *w1l, *w2h, *w2l, *wsh, *wsl;
    cudaGetSymbolAddress((void**)&xh, d_xh);
    cudaGetSymbolAddress((void**)&xl, d_xl);
    cudaGetSymbolAddress((void**)&axh, d_axh);
    cudaGetSymbolAddress((void**)&axl, d_axl);
    cudaGetSymbolAddress((void**)&h1p, d_h1p);
    cudaGetSymbolAddress((void**)&ahh, d_ahh);
    cudaGetSymbolAddress((void**)&ahl, d_ahl);
    cudaGetSymbolAddress((void**)&w1h, d_w1h);
    cudaGetSymbolAddress((void**)&w1l, d_w1l);
    cudaGetSymbolAddress((void**)&w2h, d_w2h);
    cudaGetSymbolAddress((void**)&w2l, d_w2l);
    cudaGetSymbolAddress((void**)&wsh, d_wsh);
    cudaGetSymbolAddress((void**)&wsl, d_wsl);

    cudaFuncSetAttribute(k_knn, cudaFuncAttributeMaxDynamicSharedMemorySize, SMTOT);
    cudaFuncSetAttribute(k_gemm1, cudaFuncAttributeMaxDynamicSharedMemorySize, GSM);
    cudaFuncSetAttribute(k_gemm2, cudaFuncAttributeMaxDynamicSharedMemorySize, GSM);

    // launch order: k_knn at index 3 (ncu captures launch #3)
    k_prep<<<NTOT / 8, 256>>>(x);                                            // 0
    k_splitw<<<(IND * OUTD + 255) / 256, 256>>>(W1, w1h, w1l, IND * OUTD);   // 1
    k_splitw<<<(IND * OUTD + 255) / 256, 256>>>(Ws, wsh, wsl, IND * OUTD);   // 2
    k_knn<<<dim3(NN / 128, NB), 256, SMTOT>>>(xh, xl, esrc, edst, we);       // 3
    k_splitw<<<(OUTD * OUTD + 255) / 256, 256>>>(W2, w2h, w2l, OUTD * OUTD); // 4
    k_aggx<<<NTOT / 2, 256>>>(x, axh, axl);                                  // 5
    k_gemm1<<<dim3(OUTD / 128, NTOT / 128), 256, GSM>>>(axh, axl, w1h, w1l, b1, h1p); // 6
    k_aggh<<<NTOT, 256>>>(h1p, ahh, ahl);                                    // 7
    k_gemm2<<<dim3(OUTD / 128, NTOT / 128), 256, GSM>>>(ahh, ahl, w2h, w2l,
                                                        xh, xl, wsh, wsl,
                                                        b2, bs, out);        // 8
}

// round 16
// speedup vs baseline: 1.3320x; 1.1527x over previous
#include <cuda_runtime.h>
#include <cuda_fp16.h>
#include <stdint.h>

#define NB 16
#define NN 2048
#define NTOT (NB*NN)
#define KNB 16
#define IND 128
#define OUTD 256
#define NEDGE (NTOT*KNB)

// ---------------- scratch ----------------
__device__ float d_sqn[NTOT];
__device__ int   d_nbr[NTOT*KNB];
__device__ __half d_xh[(size_t)NTOT*IND];
__device__ __half d_xl[(size_t)NTOT*IND];
__device__ __half d_axh[(size_t)NTOT*IND];
__device__ __half d_axl[(size_t)NTOT*IND];
__device__ uint32_t d_h1p[(size_t)NTOT*OUTD];
__device__ __half d_ahh[(size_t)NTOT*OUTD];
__device__ __half d_ahl[(size_t)NTOT*OUTD];
__device__ __half d_w1h[IND*OUTD],  d_w1l[IND*OUTD];
__device__ __half d_w2h[OUTD*OUTD], d_w2l[OUTD*OUTD];
__device__ __half d_wsh[IND*OUTD],  d_wsl[IND*OUTD];

// ---------------- helpers ----------------
__device__ __forceinline__ uint32_t smem_u32(const void* p) {
    uint32_t a;
    asm("{ .reg .u64 t; cvta.to.shared.u64 t, %1; cvt.u32.u64 %0, t; }" : "=r"(a) : "l"(p));
    return a;
}
__device__ __forceinline__ void cpa16(uint32_t dst, const void* src) {
    asm volatile("cp.async.cg.shared.global [%0], [%1], 16;" :: "r"(dst), "l"(src));
}
__device__ __forceinline__ void cp_commit() { asm volatile("cp.async.commit_group;"); }
__device__ __forceinline__ void cp_wait0()  { asm volatile("cp.async.wait_group 0;"); }
__device__ __forceinline__ void ldsm4(uint32_t* r, uint32_t a) {
    asm volatile("ldmatrix.sync.aligned.m8n8.x4.shared.b16 {%0,%1,%2,%3}, [%4];"
        : "=r"(r[0]), "=r"(r[1]), "=r"(r[2]), "=r"(r[3]) : "r"(a));
}
__device__ __forceinline__ void ldsm2t(uint32_t* r, uint32_t a) {
    asm volatile("ldmatrix.sync.aligned.m8n8.x2.trans.shared.b16 {%0,%1}, [%2];"
        : "=r"(r[0]), "=r"(r[1]) : "r"(a));
}
__device__ __forceinline__ void mma16816(float* c, const uint32_t* a, const uint32_t* b) {
    asm volatile("mma.sync.aligned.m16n8k16.row.col.f32.f16.f16.f32 "
        "{%0,%1,%2,%3}, {%4,%5,%6,%7}, {%8,%9}, {%0,%1,%2,%3};"
        : "+f"(c[0]), "+f"(c[1]), "+f"(c[2]), "+f"(c[3])
        : "r"(a[0]), "r"(a[1]), "r"(a[2]), "r"(a[3]), "r"(b[0]), "r"(b[1]));
}

// ---------------- prep: sqn + 2-way fp16 split of x ----------------
__global__ __launch_bounds__(256) void k_prep(const float* __restrict__ x) {
    const int row = blockIdx.x * 8 + (threadIdx.x >> 5);
    const int lane = threadIdx.x & 31;
    float4 v = *(const float4*)(x + (size_t)row * IND + lane * 4);
    float s = v.x*v.x + v.y*v.y + v.z*v.z + v.w*v.w;
#pragma unroll
    for (int o = 16; o > 0; o >>= 1) s += __shfl_xor_sync(0xffffffffu, s, o);
    if (lane == 0) d_sqn[row] = s;
    float f[4] = {v.x, v.y, v.z, v.w};
    __half h[4], l[4];
#pragma unroll
    for (int j = 0; j < 4; j++) {
        h[j] = __float2half_rn(f[j]);
        l[j] = __float2half_rn(f[j] - __half2float(h[j]));
    }
    const size_t o = (size_t)row * IND + lane * 4;
    *(uint2*)(d_xh + o) = *(uint2*)h;
    *(uint2*)(d_xl + o) = *(uint2*)l;
}

__global__ void k_splitw(const float* __restrict__ s, __half* __restrict__ hi,
                         __half* __restrict__ lo, int n) {
    int i = blockIdx.x * blockDim.x + threadIdx.x;
    if (i >= n) return;
    float f = s[i];
    __half h = __float2half_rn(f);
    hi[i] = h;
    lo[i] = __float2half_rn(f - __half2float(h));
}

// ---------------- kNN: fp16 HMMA, chunk=32, 2 CTAs/SM -----------------------
#define PB 272
#define TQB (128*PB)
#define TCB (32*PB)
#define SQ 0
#define SC (2*TQB)
#define SCSQ (SC + 4*TCB)
#define SMTOT (SCSQ + 2*32*4)
#define NCH (NN/32)

// parallel sorted-insert: O(1) dependency depth. caller guarantees key < bd[15].
__device__ __forceinline__ void ins16par(float* bd, uint32_t* bi, float key, uint32_t idx) {
    bool c[16];
#pragma unroll
    for (int j = 0; j < 15; j++) c[j] = (bd[j] > key);
    c[15] = true;
#pragma unroll
    for (int j = 15; j > 0; j--) {
        float    nb = c[j-1] ? bd[j-1] : key;
        uint32_t ni = c[j-1] ? bi[j-1] : idx;
        bd[j] = c[j] ? nb : bd[j];
        bi[j] = c[j] ? ni : bi[j];
    }
    bd[0] = c[0] ? key : bd[0];
    bi[0] = c[0] ? idx : bi[0];
}

// compare-exchange (strict > on key; equal keys keep original (idx-asc) order)
__device__ __forceinline__ void ce(float& ka, int& ia, float& kb, int& ib) {
    bool sw = ka > kb;
    float tk = sw ? kb : ka; kb = sw ? ka : kb; ka = tk;
    int   ti = sw ? ib : ia; ib = sw ? ia : ib; ia = ti;
}

__global__ __launch_bounds__(256, 2)
void k_knn(const __half* __restrict__ xh, const __half* __restrict__ xl,
           float* __restrict__ esrc, float* __restrict__ edst, int we) {
    extern __shared__ char sm[];
    const uint32_t smb = smem_u32(sm);
    float* csq = (float*)(sm + SCSQ);
    const int t = threadIdx.x, w = t >> 5, lane = t & 31;
    const int b = blockIdx.y, qb = blockIdx.x * 128, gbase = b * NN;
    const float FINF = __int_as_float(0x7f800000);
    const __half* xs[2] = {xh, xl};

    // prologue: 2 query split tiles + candidate chunk 0
    for (int s = 0; s < 2; s++) {
        for (int it = t; it < 2048; it += 256) {
            int row = it >> 4, c = it & 15;
            cpa16(smb + SQ + s*TQB + row*PB + c*16,
                  xs[s] + ((size_t)(gbase + qb + row) << 7) + c*8);
        }
        for (int it = t; it < 512; it += 256) {
            int row = it >> 4, c = it & 15;
            cpa16(smb + SC + s*TCB + row*PB + c*16,
                  xs[s] + ((size_t)(gbase + row) << 7) + c*8);
        }
    }
    if (t < 32) csq[t] = d_sqn[gbase + t];
    cp_commit();

    const int q = lane & 3;
    const bool odd = (lane & 1) != 0;
    const int myrow = w * 16 + (lane >> 2) + (odd ? 8 : 0);
    const int qrow = qb + myrow;
    const int lid = q >> 1;
    const uint32_t aoff_base = smb + SQ + (w*16 + (lane & 15))*PB + (lane >> 4)*16;
    const uint32_t bcol = ((lane >> 4)*8 + (lane & 7))*PB + ((lane >> 3) & 1)*16;

    float bd0[16];
    uint32_t bi0[16];
#pragma unroll
    for (int j = 0; j < 16; j++) { bd0[j] = FINF; bi0[j] = 0; }

    for (int i = 0; i < NCH; i++) {
        cp_wait0();
        __syncthreads();
        const int buf = i & 1;
        if (i + 1 < NCH) {
            const int nb_ = (i + 1) & 1, cb2 = (i + 1) * 32;
            for (int s = 0; s < 2; s++)
                for (int it = t; it < 512; it += 256) {
                    int row = it >> 4, c = it & 15;
                    cpa16(smb + SC + (nb_*2 + s)*TCB + row*PB + c*16,
                          xs[s] + ((size_t)(gbase + cb2 + row) << 7) + c*8);
                }
            if (t < 32) csq[nb_ * 32 + t] = d_sqn[gbase + cb2 + t];
            cp_commit();
        }
        const uint32_t chB = smb + SC + (buf*2) * TCB + bcol;
        const float* cs = csq + buf * 32;
        const int cb = i * 32;

        float acc[4][4];
#pragma unroll
        for (int nt = 0; nt < 4; nt++)
#pragma unroll
            for (int v = 0; v < 4; v++) acc[nt][v] = 0.f;

#pragma unroll 2
        for (int ks = 0; ks < 8; ks++) {
            uint32_t afh[4], afl[4];
            const uint32_t aaddr = aoff_base + ks*32;
            ldsm4(afh, aaddr);
            ldsm4(afl, aaddr + TQB);
#pragma unroll
            for (int p = 0; p < 2; p++) {
                const uint32_t bbase = chB + p*(16*PB) + ks*32;
                uint32_t bh[4], bl[4];
                ldsm4(bh, bbase);
                ldsm4(bl, bbase + TCB);
                mma16816(acc[2*p],     afh, bh);
                mma16816(acc[2*p],     afh, bl);
                mma16816(acc[2*p],     afl, bh);
                mma16816(acc[2*p + 1], afh, bh + 2);
                mma16816(acc[2*p + 1], afh, bl + 2);
                mma16816(acc[2*p + 1], afl, bh + 2);
            }
        }

        // selection: lane-pair shuffle -> one row/lane, 4 contiguous cols;
        // then 4-key sort network + nested gated inserts (fewer warp bubbles)
        const bool diag = (cb >= qb) && (cb < qb + 128);
#pragma unroll
        for (int nt = 0; nt < 4; nt++) {
            const int cl = nt*8 + 2*q;
            const float2 cq = *(const float2*)(cs + cl);
            float k00 = fmaf(-2.f, acc[nt][0], cq.x);
            float k01 = fmaf(-2.f, acc[nt][1], cq.y);
            float k10 = fmaf(-2.f, acc[nt][2], cq.x);
            float k11 = fmaf(-2.f, acc[nt][3], cq.y);
            float r0v = __shfl_xor_sync(0xffffffffu, odd ? k00 : k10, 1);
            float r1v = __shfl_xor_sync(0xffffffffu, odd ? k01 : k11, 1);
            float key0 = odd ? r0v : k00;
            float key1 = odd ? r1v : k01;
            float key2 = odd ? k10 : r0v;
            float key3 = odd ? k11 : r1v;
            const int ci = cb + nt*8 + ((q >> 1) << 2);
            if (diag) {
                if (qrow == ci)     key0 = FINF;
                if (qrow == ci + 1) key1 = FINF;
                if (qrow == ci + 2) key2 = FINF;
                if (qrow == ci + 3) key3 = FINF;
            }
            int i0 = ci, i1 = ci + 1, i2 = ci + 2, i3 = ci + 3;
            // sort 4 (key,idx) ascending by key (stable on equals)
            ce(key0, i0, key1, i1);
            ce(key2, i2, key3, i3);
            ce(key0, i0, key2, i2);
            ce(key1, i1, key3, i3);
            ce(key1, i1, key2, i2);
            // nested gated inserts: bubble j runs only if some lane has >= j+1 inserts
            if (key0 < bd0[15]) {
                ins16par(bd0, bi0, key0, (uint32_t)i0);
                if (key1 < bd0[15]) {
                    ins16par(bd0, bi0, key1, (uint32_t)i1);
                    if (key2 < bd0[15]) {
                        ins16par(bd0, bi0, key2, (uint32_t)i2);
                        if (key3 < bd0[15]) {
                            ins16par(bd0, bi0, key3, (uint32_t)i3);
                        }
                    }
                }
            }
        }
    }
    __syncthreads();

    // dump lists into the (now dead) query tile area: 2 lists per row
    float* dk = (float*)(sm + SQ);
    int*   di = (int*)(sm + SQ + 32768);
#pragma unroll
    for (int j = 0; j < 16; j++) {
        dk[(myrow*2 + lid)*16 + j] = bd0[j];
        di[(myrow*2 + lid)*16 + j] = (int)bi0[j];
    }
    __syncthreads();

    // 2-way merge per query (lexicographic (key, idx) == top_k tie-break)
    if (t < 128) {
        const float* ka  = dk + t*32;
        const float* kb2 = ka + 16;
        const int*   ia  = di + t*32;
        const int*   ib  = ia + 16;
        int pa = 0, pb = 0;
        int qg = gbase + qb + t;
#pragma unroll 1
        for (int k = 0; k < 16; k++) {
            float kva = ka[pa], kvb = kb2[pb];
            int   iva = ia[pa], ivb = ib[pb];
            bool takeA = (kva < kvb) || (kva == kvb && iva < ivb);
            int sel = takeA ? iva : ivb;
            if (takeA) pa++; else pb++;
            int sg = gbase + sel;
            size_t e = (size_t)qg * KNB + k;
            d_nbr[e] = sg;
            if (we) { esrc[e] = (float)sg; edst[e] = (float)qg; }
        }
    }
}

// ---------------- agg(x): 128-dim fp32 gather, 2 nodes/block ---------------
__global__ __launch_bounds__(256) void k_aggx(const float* __restrict__ x,
                                              __half* __restrict__ oh,
                                              __half* __restrict__ ol) {
    const int node = blockIdx.x * 2 + (threadIdx.x >> 7);
    const int t = threadIdx.x & 127;
    __shared__ int nb_s[2][KNB];
    if (t < KNB) nb_s[threadIdx.x >> 7][t] = d_nbr[(size_t)node * KNB + t];
    __syncthreads();
    const int* nbp = nb_s[threadIdx.x >> 7];
    const float norm = 1.0f / 17.0f;
    float acc = 0.f;
#pragma unroll
    for (int k = 0; k < KNB; k++) acc += x[(size_t)nbp[k] * IND + t] * norm;
    acc += x[(size_t)node * IND + t] * norm;
    __half h = __float2half_rn(acc);
    oh[(size_t)node * IND + t] = h;
    ol[(size_t)node * IND + t] = __float2half_rn(acc - __half2float(h));
}

// ---------------- agg(h1): 256-dim packed gather ----------------------------
__global__ __launch_bounds__(256) void k_aggh(const uint32_t* __restrict__ gp,
                                              __half* __restrict__ oh,
                                              __half* __restrict__ ol) {
    const int node = blockIdx.x;
    const int t = threadIdx.x;
    __shared__ int nb_s[KNB];
    if (t < KNB) nb_s[t] = d_nbr[(size_t)node * KNB + t];
    __syncthreads();
    const float norm = 1.0f / 17.0f;
    float acc = 0.f;
#pragma unroll
    for (int k = 0; k < KNB; k++) {
        uint32_t p = gp[(size_t)nb_s[k] * OUTD + t];
        acc += (__half2float(__ushort_as_half((unsigned short)(p & 0xffff)))
              + __half2float(__ushort_as_half((unsigned short)(p >> 16)))) * norm;
    }
    {
        uint32_t p = gp[(size_t)node * OUTD + t];
        acc += (__half2float(__ushort_as_half((unsigned short)(p & 0xffff)))
              + __half2float(__ushort_as_half((unsigned short)(p >> 16)))) * norm;
    }
    __half h = __float2half_rn(acc);
    oh[(size_t)node * OUTD + t] = h;
    ol[(size_t)node * OUTD + t] = __float2half_rn(acc - __half2float(h));
}

// ---------------- GEMM smem layout ----------------
#define GAP 80
#define GBP 272
#define AH0 0
#define AL0 10240
#define AH1 20480
#define AL1 30720
#define WH0 40960
#define WL0 49664
#define WH1 58368
#define WL1 67072
#define GSM 75776

// ---------------- GEMM1: h1 = relu(ax@W1 + b1) -> packed (h,l) --------------
__global__ __launch_bounds__(256)
void k_gemm1(const __half* __restrict__ Ahi, const __half* __restrict__ Alo,
             const __half* __restrict__ Whi, const __half* __restrict__ Wlo,
             const float* __restrict__ bias, uint32_t* __restrict__ Cp) {
    extern __shared__ char sm[];
    const uint32_t smb = smem_u32(sm);
    const int t = threadIdx.x, w = t >> 5, lane = t & 31;
    const int nbb = blockIdx.x * 128, mb = blockIdx.y * 128;
    const int wm = (w >> 1) * 32, wn = (w & 1) * 64;
    const int Kd = IND, nchunk = IND / 32;

    for (int it = t; it < 512; it += 256) {
        int row = it >> 2, c = it & 3;
        cpa16(smb + AH0 + row*GAP + c*16, Ahi + (size_t)(mb + row)*Kd + c*8);
        cpa16(smb + AL0 + row*GAP + c*16, Alo + (size_t)(mb + row)*Kd + c*8);
    }
    for (int it = t; it < 512; it += 256) {
        int row = it >> 4, c = it & 15;
        cpa16(smb + WH0 + row*GBP + c*16, Whi + (size_t)row*OUTD + nbb + c*8);
        cpa16(smb + WL0 + row*GBP + c*16, Wlo + (size_t)row*OUTD + nbb + c*8);
    }
    cp_commit();

    float acc[2][8][4];
#pragma unroll
    for (int mt = 0; mt < 2; mt++)
#pragma unroll
        for (int nt = 0; nt < 8; nt++)
#pragma unroll
            for (int v = 0; v < 4; v++) acc[mt][nt][v] = 0.f;

    for (int i = 0; i < nchunk; i++) {
        cp_wait0();
        __syncthreads();
        if (i + 1 < nchunk) {
            uint32_t ah = ((i + 1) & 1) ? AH1 : AH0, al = ((i + 1) & 1) ? AL1 : AL0;
            uint32_t wh = ((i + 1) & 1) ? WH1 : WH0, wl = ((i + 1) & 1) ? WL1 : WL0;
            int kc = (i + 1) * 32;
            for (int it = t; it < 512; it += 256) {
                int row = it >> 2, c = it & 3;
                cpa16(smb + ah + row*GAP + c*16, Ahi + (size_t)(mb + row)*Kd + kc + c*8);
                cpa16(smb + al + row*GAP + c*16, Alo + (size_t)(mb + row)*Kd + kc + c*8);
            }
            for (int it = t; it < 512; it += 256) {
                int row = it >> 4, c = it & 15;
                cpa16(smb + wh + row*GBP + c*16, Whi + (size_t)(kc + row)*OUTD + nbb + c*8);
                cpa16(smb + wl + row*GBP + c*16, Wlo + (size_t)(kc + row)*OUTD + nbb + c*8);
            }
            cp_commit();
        }
        const uint32_t ah = smb + ((i & 1) ? AH1 : AH0), al = smb + ((i & 1) ? AL1 : AL0);
        const uint32_t wh = smb + ((i & 1) ? WH1 : WH0), wl = smb + ((i & 1) ? WL1 : WL0);
#pragma unroll
        for (int ks = 0; ks < 2; ks++) {
            uint32_t afh[2][4], afl[2][4];
#pragma unroll
            for (int mt = 0; mt < 2; mt++) {
                uint32_t aoff = (wm + mt*16 + (lane & 15))*GAP + ks*32 + (lane >> 4)*16;
                ldsm4(afh[mt], ah + aoff);
                ldsm4(afl[mt], al + aoff);
            }
#pragma unroll
            for (int nt = 0; nt < 8; nt++) {
                uint32_t boff = (ks*16 + (lane & 15))*GBP + (wn + nt*8)*2;
                uint32_t bfh[2], bfl[2];
                ldsm2t(bfh, wh + boff);
                ldsm2t(bfl, wl + boff);
#pragma unroll
                for (int mt = 0; mt < 2; mt++) {
                    mma16816(acc[mt][nt], afh[mt], bfh);
                    mma16816(acc[mt][nt], afh[mt], bfl);
                    mma16816(acc[mt][nt], afl[mt], bfh);
                }
            }
        }
    }
#pragma unroll
    for (int mt = 0; mt < 2; mt++) {
#pragma unroll
        for (int nt = 0; nt < 8; nt++) {
            int m0 = mb + wm + mt*16 + (lane >> 2);
            int n0 = nbb + wn + nt*8 + 2*(lane & 3);
            float b0 = bias[n0], b1v = bias[n0 + 1];
#pragma unroll
            for (int rr = 0; rr < 2; rr++) {
                int m = m0 + rr * 8;
                float v0 = fmaxf(acc[mt][nt][rr*2 + 0] + b0, 0.f);
                float v1 = fmaxf(acc[mt][nt][rr*2 + 1] + b1v, 0.f);
                __half h0 = __float2half_rn(v0), h1 = __float2half_rn(v1);
                __half l0 = __float2half_rn(v0 - __half2float(h0));
                __half l1 = __float2half_rn(v1 - __half2float(h1));
                uint2 pk;
                pk.x = (uint32_t)__half_as_ushort(h0) | ((uint32_t)__half_as_ushort(l0) << 16);
                pk.y = (uint32_t)__half_as_ushort(h1) | ((uint32_t)__half_as_ushort(l1) << 16);
                *(uint2*)(Cp + (size_t)m * OUTD + n0) = pk;
            }
        }
    }
}

// ---------------- GEMM2: out = ah@W2 + x@Ws + (b2+bs) -----------------------
__global__ __launch_bounds__(256)
void k_gemm2(const __half* __restrict__ A1h, const __half* __restrict__ A1l,
             const __half* __restrict__ W1h_, const __half* __restrict__ W1l_,
             const __half* __restrict__ A2h, const __half* __restrict__ A2l,
             const __half* __restrict__ W2h_, const __half* __restrict__ W2l_,
             const float* __restrict__ bias1, const float* __restrict__ bias2,
             float* __restrict__ C) {
    extern __shared__ char sm[];
    const uint32_t smb = smem_u32(sm);
    const int t = threadIdx.x, w = t >> 5, lane = t & 31;
    const int nbb = blockIdx.x * 128, mb = blockIdx.y * 128;
    const int wm = (w >> 1) * 32, wn = (w & 1) * 64;
    const int NC1 = OUTD / 32;
    const int NC = NC1 + IND / 32;

    auto prefetch = [&](int j, int pb) {
        uint32_t ah = pb ? AH1 : AH0, al = pb ? AL1 : AL0;
        uint32_t wh = pb ? WH1 : WH0, wl = pb ? WL1 : WL0;
        const __half *Ah, *Al, *Wh, *Wl;
        int Kd, kc;
        if (j < NC1) { Ah = A1h; Al = A1l; Wh = W1h_; Wl = W1l_; Kd = OUTD; kc = j * 32; }
        else         { Ah = A2h; Al = A2l; Wh = W2h_; Wl = W2l_; Kd = IND;  kc = (j - NC1) * 32; }
        for (int it = t; it < 512; it += 256) {
            int row = it >> 2, c = it & 3;
            cpa16(smb + ah + row*GAP + c*16, Ah + (size_t)(mb + row)*Kd + kc + c*8);
            cpa16(smb + al + row*GAP + c*16, Al + (size_t)(mb + row)*Kd + kc + c*8);
        }
        for (int it = t; it < 512; it += 256) {
            int row = it >> 4, c = it & 15;
            cpa16(smb + wh + row*GBP + c*16, Wh + (size_t)(kc + row)*OUTD + nbb + c*8);
            cpa16(smb + wl + row*GBP + c*16, Wl + (size_t)(kc + row)*OUTD + nbb + c*8);
        }
        cp_commit();
    };

    prefetch(0, 0);

    float acc[2][8][4];
#pragma unroll
    for (int mt = 0; mt < 2; mt++)
#pragma unroll
        for (int nt = 0; nt < 8; nt++)
#pragma unroll
            for (int v = 0; v < 4; v++) acc[mt][nt][v] = 0.f;

    for (int i = 0; i < NC; i++) {
        cp_wait0();
        __syncthreads();
        if (i + 1 < NC) prefetch(i + 1, (i + 1) & 1);
        const uint32_t ah = smb + ((i & 1) ? AH1 : AH0), al = smb + ((i & 1) ? AL1 : AL0);
        const uint32_t wh = smb + ((i & 1) ? WH1 : WH0), wl = smb + ((i & 1) ? WL1 : WL0);
#pragma unroll
        for (int ks = 0; ks < 2; ks++) {
            uint32_t afh[2][4], afl[2][4];
#pragma unroll
            for (int mt = 0; mt < 2; mt++) {
                uint32_t aoff = (wm + mt*16 + (lane & 15))*GAP + ks*32 + (lane >> 4)*16;
                ldsm4(afh[mt], ah + aoff);
                ldsm4(afl[mt], al + aoff);
            }
#pragma unroll
            for (int nt = 0; nt < 8; nt++) {
                uint32_t boff = (ks*16 + (lane & 15))*GBP + (wn + nt*8)*2;
                uint32_t bfh[2], bfl[2];
                ldsm2t(bfh, wh + boff);
                ldsm2t(bfl, wl + boff);
#pragma unroll
                for (int mt = 0; mt < 2; mt++) {
                    mma16816(acc[mt][nt], afh[mt], bfh);
                    mma16816(acc[mt][nt], afh[mt], bfl);
                    mma16816(acc[mt][nt], afl[mt], bfh);
                }
            }
        }
    }
#pragma unroll
    for (int mt = 0; mt < 2; mt++) {
#pragma unroll
        for (int nt = 0; nt < 8; nt++) {
            int m0 = mb + wm + mt*16 + (lane >> 2);
            int n0 = nbb + wn + nt*8 + 2*(lane & 3);
            float b0 = bias1[n0] + bias2[n0];
            float b1v = bias1[n0 + 1] + bias2[n0 + 1];
            float2 v0 = make_float2(acc[mt][nt][0] + b0, acc[mt][nt][1] + b1v);
            float2 v1 = make_float2(acc[mt][nt][2] + b0, acc[mt][nt][3] + b1v);
            *(float2*)(C + (size_t)m0 * OUTD + n0) = v0;
            *(float2*)(C + (size_t)(m0 + 8) * OUTD + n0) = v1;
        }
    }
}

// ---------------- launch ----------------
extern "C" void kernel_launch(void* const* d_in, const int* in_sizes, int n_in,
                              void* d_out, int out_size) {
    const float* x  = (const float*)d_in[0];
    const float* W1 = (const float*)d_in[2];
    const float* b1 = (const float*)d_in[3];
    const float* W2 = (const float*)d_in[4];
    const float* b2 = (const float*)d_in[5];
    const float* Ws = (const float*)d_in[6];
    const float* bs = (const float*)d_in[7];

    float* out  = (float*)d_out;
    float* esrc = out + (size_t)NTOT * OUTD;
    float* edst = esrc + NEDGE;
    int we = (out_size >= (int)((size_t)NTOT * OUTD + 2 * NEDGE)) ? 1 : 0;

    __half *xh, *xl, *axh, *axl, *ahh, *ahl;
    uint32_t *h1p;
    __half *w1h, *w1l, *w2h, *w2l, *wsh, *wsl;
    cudaGetSymbolAddress((void**)&xh, d_xh);
    cudaGetSymbolAddress((void**)&xl, d_xl);
    cudaGetSymbolAddress((void**)&axh, d_axh);
    cudaGetSymbolAddress((void**)&axl, d_axl);
    cudaGetSymbolAddress((void**)&h1p, d_h1p);
    cudaGetSymbolAddress((void**)&ahh, d_ahh);
    cudaGetSymbolAddress((void**)&ahl, d_ahl);
    cudaGetSymbolAddress((void**)&w1h, d_w1h);
    cudaGetSymbolAddress((void**)&w1l, d_w1l);
    cudaGetSymbolAddress((void**)&w2h, d_w2h);
    cudaGetSymbolAddress((void**)&w2l, d_w2l);
    cudaGetSymbolAddress((void**)&wsh, d_wsh);
    cudaGetSymbolAddress((void**)&wsl, d_wsl);

    cudaFuncSetAttribute(k_knn, cudaFuncAttributeMaxDynamicSharedMemorySize, SMTOT);
    cudaFuncSetAttribute(k_gemm1, cudaFuncAttributeMaxDynamicSharedMemorySize, GSM);
    cudaFuncSetAttribute(k_gemm2, cudaFuncAttributeMaxDynamicSharedMemorySize, GSM);

    // launch order: k_knn at index 3 (ncu captures launch #3)
    k_prep<<<NTOT / 8, 256>>>(x);                                            // 0
    k_splitw<<<(IND * OUTD + 255) / 256, 256>>>(W1, w1h, w1l, IND * OUTD);   // 1
    k_splitw<<<(IND * OUTD + 255) / 256, 256>>>(Ws, wsh, wsl, IND * OUTD);   // 2
    k_knn<<<dim3(NN / 128, NB), 256, SMTOT>>>(xh, xl, esrc, edst, we);       // 3
    k_splitw<<<(OUTD * OUTD + 255) / 256, 256>>>(W2, w2h, w2l, OUTD * OUTD); // 4
    k_aggx<<<NTOT / 2, 256>>>(x, axh, axl);                                  // 5
    k_gemm1<<<dim3(OUTD / 128, NTOT / 128), 256, GSM>>>(axh, axl, w1h, w1l, b1, h1p); // 6
    k_aggh<<<NTOT, 256>>>(h1p, ahh, ahl);                                    // 7
    k_gemm2<<<dim3(OUTD / 128, NTOT / 128), 256, GSM>>>(ahh, ahl, w2h, w2l,
                                                        xh, xl, wsh, wsl,
                                                        b2, bs, out);        // 8
}